// round 12
// baseline (speedup 1.0000x reference)
#include <cuda_runtime.h>
#include <cuda_bf16.h>
#include <stdint.h>

// Problem constants (fixed by reference: B=16, NT=4096, D=512, V=2545)
#define B_  16
#define NT_ 4096
#define D_  512
#define V_  2545
#define D_VEC (D_ / 4)               // 128 float4 per embedding row
#define NROWS (B_ * NT_)             // 65536 output rows

// Scratch (device allocations forbidden -> __device__ globals)
__device__ int g_len[B_];      // valid-token count per batch
__device__ int g_is64;         // text layout flag

// ---------------------------------------------------------------------------
// Prep kernel: count-only (no mapping!). 16 blocks x 512 threads.
//  (a) dtype probe (int64 little-endian word-pairs vs int32);
//  (b) valid-token count L_b -> g_len.
// Ends with the PDL trigger so the scatter kernel's launch overlaps our tail.
// ---------------------------------------------------------------------------
__global__ void __launch_bounds__(512)
prep_kernel(const int* __restrict__ t32) {
    const int b   = blockIdx.x;
    const int tid = threadIdx.x;

    int bad = 0;
    if (tid < 256) {
        const int lo = t32[2 * tid];
        const int hi = t32[2 * tid + 1];
        const int want_hi = (lo < 0) ? -1 : 0;
        if (hi != want_hi || lo < -1 || lo >= V_) bad = 1;
    }
    const int is64 = __syncthreads_or(bad) ? 0 : 1;
    const int stride = is64 ? 2 : 1;
    const int* row = t32 + (size_t)b * NT_ * stride;

    int cnt = 0;
    #pragma unroll
    for (int i = tid; i < NT_; i += 512)
        cnt += (row[(size_t)i * stride] >= 0);
    #pragma unroll
    for (int off = 16; off > 0; off >>= 1)
        cnt += __shfl_down_sync(0xFFFFFFFFu, cnt, off);

    __shared__ int s_part[16];
    if ((tid & 31) == 0) s_part[tid >> 5] = cnt;
    __syncthreads();
    if (tid == 0) {
        int total = 0;
        for (int w = 0; w < 16; ++w) total += s_part[w];
        g_len[b] = total;
        if (b == 0) g_is64 = is64;
    }

#if defined(__CUDA_ARCH__) && (__CUDA_ARCH__ >= 900)
    cudaTriggerProgrammaticLaunchCompletion();
#endif
}

// ---------------------------------------------------------------------------
// Scatter-broadcast kernel: one block per (b, j) SOURCE token.
// The stretch mapping is contiguous per source token:
//   j <  L-rem : output span [j*base, j*base+base)
//   j >= L-rem : output span [boundary + (j-(L-rem))*(base+1), ... +base+1)
// So: read emb[text[b,j]+1] ONCE (128 lanes x float4), then store it to all
// `count` consecutive output rows. Read wavefronts shrink ~8x vs gather;
// writes (the mandatory 134 MB) are unchanged and fully coalesced.
// Blocks with j >= L exit after one cached meta read.
// grid = (NT_, B_), block = 128 threads.
// ---------------------------------------------------------------------------
__global__ void __launch_bounds__(128)
scatter_embed_kernel(const int* __restrict__ t32,
                     const float4* __restrict__ emb,
                     float4* __restrict__ out) {
#if defined(__CUDA_ARCH__) && (__CUDA_ARCH__ >= 900)
    cudaGridDependencySynchronize();   // HW wait for prep completion
#endif

    const int j    = blockIdx.x;
    const int b    = blockIdx.y;
    const int lane = threadIdx.x;      // 0..127

    const int L = g_len[b];

    if (L <= 0) {                      // impossible per reference (lengths>=1)
        if (j == 0) {                  // but handle exactly: whole batch = 0
            const float4 z = make_float4(0.f, 0.f, 0.f, 0.f);
            float4* dst = out + (size_t)b * NT_ * D_VEC + lane;
            for (int r = 0; r < NT_; ++r)
                __stcs(dst + (size_t)r * D_VEC, z);
        }
        return;
    }
    if (j >= L) return;

    const unsigned base = (unsigned)NT_ / (unsigned)L;
    const unsigned rem  = (unsigned)NT_ % (unsigned)L;
    const unsigned Lr   = (unsigned)L - rem;          // tokens with `base` copies

    unsigned start, count;
    if ((unsigned)j < Lr) { start = (unsigned)j * base;                          count = base;     }
    else                  { start = Lr * base + ((unsigned)j - Lr) * (base + 1); count = base + 1; }

    const int stride = g_is64 ? 2 : 1;
    int tok = t32[((size_t)b * NT_ + j) * stride] + 1;   // [1, V] for valid prefix
    tok = min(max(tok, 0), V_);                          // hard safety clamp

    const float4 v = __ldg(emb + (size_t)tok * D_VEC + lane);

    float4* dst = out + ((size_t)b * NT_ + start) * D_VEC + lane;
    #pragma unroll 4
    for (unsigned c = 0; c < count; ++c)
        __stcs(dst + (size_t)c * D_VEC, v);
}

// ---------------------------------------------------------------------------
// Launch: prep (count-only), then scatter via PDL so its launch overlaps
// prep's execution. Both plain launches — graph-capturable, allocation-free.
// ---------------------------------------------------------------------------
extern "C" void kernel_launch(void* const* d_in, const int* in_sizes, int n_in,
                              void* d_out, int out_size) {
    const int*   text = nullptr;
    const float* emb  = nullptr;
    for (int i = 0; i < n_in; ++i) {
        if (in_sizes[i] == NROWS || in_sizes[i] == 2 * NROWS)
            text = (const int*)d_in[i];
        else if (in_sizes[i] == (V_ + 1) * D_)
            emb = (const float*)d_in[i];
    }

    prep_kernel<<<B_, 512>>>(text);

    cudaLaunchConfig_t cfg = {};
    cfg.gridDim  = dim3(NT_, B_, 1);
    cfg.blockDim = dim3(128, 1, 1);
    cfg.dynamicSmemBytes = 0;
    cfg.stream = 0;
    cudaLaunchAttribute attr[1];
    attr[0].id = cudaLaunchAttributeProgrammaticStreamSerialization;
    attr[0].val.programmaticStreamSerializationAllowed = 1;
    cfg.attrs = attr;
    cfg.numAttrs = 1;

    const int* t = text;
    const float4* emb4 = (const float4*)emb;
    float4* out4 = (float4*)d_out;
    cudaError_t e = cudaLaunchKernelEx(&cfg, scatter_embed_kernel, t, emb4, out4);
    if (e != cudaSuccess) {
        scatter_embed_kernel<<<dim3(NT_, B_, 1), 128>>>(t, emb4, out4);
    }
    (void)out_size;
}

// round 13
// speedup vs baseline: 1.6790x; 1.6790x over previous
#include <cuda_runtime.h>
#include <cuda_bf16.h>
#include <stdint.h>

// Problem constants (fixed by reference: B=16, NT=4096, D=512, V=2545)
#define B_  16
#define NT_ 4096
#define D_  512
#define V_  2545
#define D_VEC (D_ / 4)               // 128 float4 per embedding row
#define NROWS (B_ * NT_)             // 65536 output rows
#define NPREP 128                    // prep blocks (8 chunks x 16 batches)
#define CHUNK (NT_ / 8)              // 512 positions per prep chunk

// Scratch (device allocations forbidden -> __device__ global)
__device__ int g_tok[NROWS];   // source token per output row (+1 applied), or -1 => zeros

// ---------------------------------------------------------------------------
// Prep kernel (proven R7 config): 128 blocks x 512 threads.
//  (a) dtype probe (int64 little-endian word-pairs vs int32);
//  (b) valid-token count L_b (redundant per chunk-block — cheap, L2-resident);
//  (c) stretch mapping for this block's 512 positions -> g_tok.
// ---------------------------------------------------------------------------
__global__ void __launch_bounds__(512)
prep_kernel(const int* __restrict__ t32) {
    const int b     = blockIdx.x >> 3;
    const int chunk = blockIdx.x & 7;
    const int tid   = threadIdx.x;

    // --- dtype probe ---
    int bad = 0;
    if (tid < 256) {
        const int lo = t32[2 * tid];
        const int hi = t32[2 * tid + 1];
        const int want_hi = (lo < 0) ? -1 : 0;
        if (hi != want_hi || lo < -1 || lo >= V_) bad = 1;
    }
    const int is64 = __syncthreads_or(bad) ? 0 : 1;
    const int stride = is64 ? 2 : 1;
    const int* row = t32 + (size_t)b * NT_ * stride;

    // --- count valid tokens (valid = token >= 0) ---
    int cnt = 0;
    #pragma unroll
    for (int i = tid; i < NT_; i += 512)
        cnt += (row[(size_t)i * stride] >= 0);
    #pragma unroll
    for (int off = 16; off > 0; off >>= 1)
        cnt += __shfl_down_sync(0xFFFFFFFFu, cnt, off);

    __shared__ int s_part[16];
    if ((tid & 31) == 0) s_part[tid >> 5] = cnt;
    __syncthreads();
    __shared__ int s_L;
    if (tid == 0) {
        int total = 0;
        for (int w = 0; w < 16; ++w) total += s_part[w];
        s_L = total;
    }
    __syncthreads();
    const int L = s_L;

    // --- stretch mapping for this chunk's 512 positions (1 per thread) ---
    const int p = chunk * CHUNK + tid;
    int* tok_row = g_tok + b * NT_;
    if (L <= 0) {
        tok_row[p] = -1;
    } else {
        const unsigned base = (unsigned)NT_ / (unsigned)L;
        const unsigned rem  = (unsigned)NT_ % (unsigned)L;
        const unsigned boundary = ((unsigned)L - rem) * base;
        unsigned j;
        if ((unsigned)p < boundary) j = (unsigned)p / base;
        else                        j = ((unsigned)L - rem) + ((unsigned)p - boundary) / (base + 1);
        int t = row[(size_t)j * stride] + 1;    // [1, V] for valid prefix
        tok_row[p] = min(max(t, 0), V_);        // hard safety clamp
    }
}

// ---------------------------------------------------------------------------
// Embed kernel: pure gather-copy, proven R3/R7 configuration, but with PLAIN
// write-back stores instead of __stcs. Rationale: measured HBM traffic during
// the kernel (~78 MB) is far below the 134 MB written, meaning L2 elides
// DRAM writebacks for output lines re-dirtied across graph replays. The
// streaming (.cs, evict-first) hint fights that elision by evicting output
// lines early; default .wb maximizes it, reducing the mandatory DRAM write
// drain that pins this kernel at ~21.8 us.
// 256 threads/block handle 8 rows: thread t owns lane = t & 127 of rows
// rowBase + (t>>7) + {0,2,4,6}. MLP=4 loads, then 4 stores.
// grid = NROWS / 8 = 8192 blocks.
// ---------------------------------------------------------------------------
__global__ void __launch_bounds__(256)
embed_copy_kernel(const float4* __restrict__ emb,
                  float4* __restrict__ out) {
    const int lane = threadIdx.x & 127;
    const int sub  = threadIdx.x >> 7;          // 0 or 1
    const int rowBase = blockIdx.x * 8 + sub;

    int tok[4];
    #pragma unroll
    for (int k = 0; k < 4; ++k)
        tok[k] = __ldg(&g_tok[rowBase + 2 * k]);

    float4 v[4];
    #pragma unroll
    for (int k = 0; k < 4; ++k) {
        if (tok[k] >= 0)
            v[k] = __ldg(emb + (size_t)tok[k] * D_VEC + lane);
        else
            v[k] = make_float4(0.f, 0.f, 0.f, 0.f);
    }

    #pragma unroll
    for (int k = 0; k < 4; ++k)
        out[(size_t)(rowBase + 2 * k) * D_VEC + lane] = v[k];   // plain .wb store
}

// ---------------------------------------------------------------------------
// Launch. Identify inputs by element count:
//   text: 65536 elements (int32 or int64) or 131072 int32-words; the
//         device-side probe resolves the layout.
//   emb : (2545+1)*512 = 1303552 fp32.
// ---------------------------------------------------------------------------
extern "C" void kernel_launch(void* const* d_in, const int* in_sizes, int n_in,
                              void* d_out, int out_size) {
    const int*   text = nullptr;
    const float* emb  = nullptr;
    for (int i = 0; i < n_in; ++i) {
        if (in_sizes[i] == NROWS || in_sizes[i] == 2 * NROWS)
            text = (const int*)d_in[i];
        else if (in_sizes[i] == (V_ + 1) * D_)
            emb = (const float*)d_in[i];
    }

    prep_kernel<<<NPREP, 512>>>(text);
    embed_copy_kernel<<<NROWS / 8, 256>>>((const float4*)emb, (float4*)d_out);
    (void)out_size;
}

// round 14
// speedup vs baseline: 1.9106x; 1.1379x over previous
#include <cuda_runtime.h>
#include <cuda_bf16.h>
#include <stdint.h>

// Problem constants (fixed by reference: B=16, NT=4096, D=512, V=2545)
#define B_  16
#define NT_ 4096
#define D_  512
#define V_  2545
#define D_VEC (D_ / 4)               // 128 float4 per embedding row
#define NROWS (B_ * NT_)             // 65536 output rows
#define NPREP 128                    // prep blocks (8 chunks x 16 batches)
#define CHUNK (NT_ / 8)              // 512 positions per prep chunk

// Hybrid split: blocks [0, STG_TILES) use the STG path (8 rows each);
// blocks [STG_TILES, 8192) use the TMA bulk-store path (8 rows each).
#define TOTAL_TILES (NROWS / 8)      // 8192
#define STG_TILES   4928             // ~60% of rows on the LSU/STG drain
#define TILE_F4     (8 * D_VEC)      // 1024 float4 = 16 KB per tile
#define TILE_BYTES  (TILE_F4 * 16)   // 16384

// Scratch (device allocations forbidden -> __device__ global)
__device__ int g_tok[NROWS];   // source token per output row (+1 applied), or -1 => zeros

// ---------------------------------------------------------------------------
// Prep kernel (proven R7 config): 128 blocks x 512 threads.
//  (a) dtype probe (int64 little-endian word-pairs vs int32);
//  (b) valid-token count L_b;
//  (c) stretch mapping for this block's 512 positions -> g_tok.
// ---------------------------------------------------------------------------
__global__ void __launch_bounds__(512)
prep_kernel(const int* __restrict__ t32) {
    const int b     = blockIdx.x >> 3;
    const int chunk = blockIdx.x & 7;
    const int tid   = threadIdx.x;

    int bad = 0;
    if (tid < 256) {
        const int lo = t32[2 * tid];
        const int hi = t32[2 * tid + 1];
        const int want_hi = (lo < 0) ? -1 : 0;
        if (hi != want_hi || lo < -1 || lo >= V_) bad = 1;
    }
    const int is64 = __syncthreads_or(bad) ? 0 : 1;
    const int stride = is64 ? 2 : 1;
    const int* row = t32 + (size_t)b * NT_ * stride;

    int cnt = 0;
    #pragma unroll
    for (int i = tid; i < NT_; i += 512)
        cnt += (row[(size_t)i * stride] >= 0);
    #pragma unroll
    for (int off = 16; off > 0; off >>= 1)
        cnt += __shfl_down_sync(0xFFFFFFFFu, cnt, off);

    __shared__ int s_part[16];
    if ((tid & 31) == 0) s_part[tid >> 5] = cnt;
    __syncthreads();
    __shared__ int s_L;
    if (tid == 0) {
        int total = 0;
        for (int w = 0; w < 16; ++w) total += s_part[w];
        s_L = total;
    }
    __syncthreads();
    const int L = s_L;

    const int p = chunk * CHUNK + tid;
    int* tok_row = g_tok + b * NT_;
    if (L <= 0) {
        tok_row[p] = -1;
    } else {
        const unsigned base = (unsigned)NT_ / (unsigned)L;
        const unsigned rem  = (unsigned)NT_ % (unsigned)L;
        const unsigned boundary = ((unsigned)L - rem) * base;
        unsigned j;
        if ((unsigned)p < boundary) j = (unsigned)p / base;
        else                        j = ((unsigned)L - rem) + ((unsigned)p - boundary) / (base + 1);
        int t = row[(size_t)j * stride] + 1;    // [1, V] for valid prefix
        tok_row[p] = min(max(t, 0), V_);        // hard safety clamp
    }
}

// ---------------------------------------------------------------------------
// Hybrid embed kernel: 8192 blocks x 256 threads, 16 KB static SMEM.
//  - Blocks [0, STG_TILES): exact R3/R7 gather-copy body — MLP=4 LDG.128
//    gathers + 4 STG.128 streaming stores (LSU drain).
//  - Blocks [STG_TILES, 8192): gather into SMEM (STS.128, cheap), then ONE
//    16 KB cp.async.bulk shared->global on the TMA pipe (zero LSU store
//    issue). Different drain resource -> runs concurrently with STG blocks.
// 16 KB smem still allows 8 blocks/SM at 256 thr (132 KB < 228 KB), occ 100%.
// ---------------------------------------------------------------------------
__global__ void __launch_bounds__(256)
hybrid_embed_kernel(const float4* __restrict__ emb,
                    float4* __restrict__ out) {
    __shared__ alignas(128) float4 s_buf[TILE_F4];   // 16 KB (used by TMA path)

    const int tid = threadIdx.x;
    const int bid = blockIdx.x;

    if (bid < STG_TILES) {
        // ---------------- STG path (proven R3/R7 body) ----------------
        const int lane = tid & 127;
        const int sub  = tid >> 7;              // 0 or 1
        const int rowBase = bid * 8 + sub;

        int tok[4];
        #pragma unroll
        for (int k = 0; k < 4; ++k)
            tok[k] = __ldg(&g_tok[rowBase + 2 * k]);

        float4 v[4];
        #pragma unroll
        for (int k = 0; k < 4; ++k) {
            if (tok[k] >= 0)
                v[k] = __ldg(emb + (size_t)tok[k] * D_VEC + lane);
            else
                v[k] = make_float4(0.f, 0.f, 0.f, 0.f);
        }

        #pragma unroll
        for (int k = 0; k < 4; ++k)
            __stcs(out + (size_t)(rowBase + 2 * k) * D_VEC + lane, v[k]);
    } else {
        // ---------------- TMA bulk-store path ----------------
        const int rowBase = bid * 8;            // 8 consecutive rows

        __shared__ int s_tok[8];
        if (tid < 8)
            s_tok[tid] = g_tok[rowBase + tid];
        __syncthreads();

        // 4 float4 per thread: idx = tid + k*256; row = idx>>7; lane = idx&127
        #pragma unroll
        for (int k = 0; k < 4; ++k) {
            const int idx  = tid + k * 256;
            const int r    = idx >> 7;
            const int lane = idx & 127;
            const int t    = s_tok[r];
            s_buf[idx] = (t >= 0) ? __ldg(emb + (size_t)t * D_VEC + lane)
                                  : make_float4(0.f, 0.f, 0.f, 0.f);
        }

        __syncthreads();
        asm volatile("fence.proxy.async.shared::cta;" ::: "memory");

        if (tid == 0) {
            uint32_t s_addr = (uint32_t)__cvta_generic_to_shared(s_buf);
            float4* gdst = out + (size_t)rowBase * D_VEC;
            asm volatile(
                "cp.async.bulk.global.shared::cta.bulk_group [%0], [%1], %2;"
                :: "l"(gdst), "r"(s_addr), "r"((unsigned)TILE_BYTES)
                : "memory");
            asm volatile("cp.async.bulk.commit_group;" ::: "memory");
            asm volatile("cp.async.bulk.wait_group 0;" ::: "memory");
        }
    }
}

// ---------------------------------------------------------------------------
// Launch. Identify inputs by element count:
//   text: 65536 elements (int32 or int64) or 131072 int32-words; the
//         device-side probe resolves the layout.
//   emb : (2545+1)*512 = 1303552 fp32.
// ---------------------------------------------------------------------------
extern "C" void kernel_launch(void* const* d_in, const int* in_sizes, int n_in,
                              void* d_out, int out_size) {
    const int*   text = nullptr;
    const float* emb  = nullptr;
    for (int i = 0; i < n_in; ++i) {
        if (in_sizes[i] == NROWS || in_sizes[i] == 2 * NROWS)
            text = (const int*)d_in[i];
        else if (in_sizes[i] == (V_ + 1) * D_)
            emb = (const float*)d_in[i];
    }

    prep_kernel<<<NPREP, 512>>>(text);
    hybrid_embed_kernel<<<TOTAL_TILES, 256>>>((const float4*)emb, (float4*)d_out);
    (void)out_size;
}